// round 12
// baseline (speedup 1.0000x reference)
#include <cuda_runtime.h>

// Problem constants (fixed: B=16, T=1024, D=1024, O=10)
#define BB 16
#define TT 1024
#define DD 1024
#define OO 10

#define CTA 128
#define WARPS 4
#define RPW 4                     // rows per warp (acc = 40 scalar regs)
#define RPC (WARPS * RPW)         // 16 rows per CTA
#define KT 128                    // d per chunk (4 floats per lane)
#define NKT (DD / KT)             // 8 chunks per row
#define W_FLOATS (OO * DD)        // 10240

__device__ float g_scores[BB * OO * TT];   // [b][o][t]
__device__ float g_wx[BB * OO * TT];       // softmaxed, [b][o][i]

// ---------------------------------------------------------------------------
// GEMV body: 4 rows x 1024 d per warp. No smem: weights stream through L1
// (40 KB, permanently hot). Plain unrolled loop — ptxas schedules the loads.
// rbase/wbase already offset by lane*4.
// ---------------------------------------------------------------------------
__device__ __forceinline__ void gemv_rows(const float* __restrict__ rbase,
                                          const float* __restrict__ wbase,
                                          float (&acc)[RPW][OO]) {
    #pragma unroll
    for (int r = 0; r < RPW; r++)
        #pragma unroll
        for (int o = 0; o < OO; o++) acc[r][o] = 0.0f;

    #pragma unroll
    for (int kt = 0; kt < NKT; kt++) {
        float4 lg[RPW];
        #pragma unroll
        for (int r = 0; r < RPW; r++)
            lg[r] = *(const float4*)(rbase + r * DD + kt * KT);
        #pragma unroll
        for (int o = 0; o < OO; o++) {
            const float4 w4 = *(const float4*)(wbase + o * DD + kt * KT);
            #pragma unroll
            for (int r = 0; r < RPW; r++) {
                acc[r][o] = fmaf(lg[r].x, w4.x, acc[r][o]);
                acc[r][o] = fmaf(lg[r].y, w4.y, acc[r][o]);
                acc[r][o] = fmaf(lg[r].z, w4.z, acc[r][o]);
                acc[r][o] = fmaf(lg[r].w, w4.w, acc[r][o]);
            }
        }
    }
}

// Reduce 40 partials across warp; lane0 writes [o][t]-layout results.
__device__ __forceinline__ void reduce_store(float (&acc)[RPW][OO], int lane,
                                             float* __restrict__ dst,
                                             int t0, float scale,
                                             const float* __restrict__ bias) {
    #pragma unroll
    for (int r = 0; r < RPW; r++)
        #pragma unroll
        for (int o = 0; o < OO; o++) {
            float v = acc[r][o];
            #pragma unroll
            for (int s = 16; s > 0; s >>= 1)
                v += __shfl_xor_sync(0xffffffffu, v, s);
            if (lane == 0) {
                if (bias) v = (v + __ldg(&bias[o])) * scale;
                dst[o * TT + t0 + r] = v;
            }
        }
}

// ---------------------------------------------------------------------------
// Kernel 1: scores[b][o][t] = (logits[b,t,:] . W[o,:] + bias[o]) / OO
// Grid 1024 x 128. No smem, no barriers: 6 CTAs/SM, 24 free-running warps.
// ---------------------------------------------------------------------------
__global__ __launch_bounds__(CTA, 6) void k_scores(const float* __restrict__ logits,
                                                   const float* __restrict__ W,
                                                   const float* __restrict__ bias) {
    const int warp = threadIdx.x >> 5;
    const int lane = threadIdx.x & 31;
    const int row0 = blockIdx.x * RPC + warp * RPW;

    float acc[RPW][OO];
    gemv_rows(logits + (size_t)row0 * DD + lane * 4, W + lane * 4, acc);

    const int b = row0 / TT;
    reduce_store(acc, lane, g_scores + b * OO * TT, row0 % TT, 1.0f / OO, bias);
}

// ---------------------------------------------------------------------------
// Kernel 2: softmax over t for each (b,o). 160 blocks x 256 threads.
// ---------------------------------------------------------------------------
__global__ __launch_bounds__(256) void k_softmax() {
    const int ro = blockIdx.x;
    const int tid = threadIdx.x;
    const float4 v = ((const float4*)&g_scores[ro * TT])[tid];

    __shared__ float red[8];

    float m = fmaxf(fmaxf(v.x, v.y), fmaxf(v.z, v.w));
    #pragma unroll
    for (int s = 16; s > 0; s >>= 1)
        m = fmaxf(m, __shfl_xor_sync(0xffffffffu, m, s));
    if ((tid & 31) == 0) red[tid >> 5] = m;
    __syncthreads();
    float mall = red[0];
    #pragma unroll
    for (int i = 1; i < 8; i++) mall = fmaxf(mall, red[i]);
    __syncthreads();

    float4 e;
    e.x = __expf(v.x - mall);
    e.y = __expf(v.y - mall);
    e.z = __expf(v.z - mall);
    e.w = __expf(v.w - mall);
    float s4 = e.x + e.y + e.z + e.w;
    #pragma unroll
    for (int s = 16; s > 0; s >>= 1)
        s4 += __shfl_xor_sync(0xffffffffu, s4, s);
    if ((tid & 31) == 0) red[tid >> 5] = s4;
    __syncthreads();
    float sall = 0.0f;
    #pragma unroll
    for (int i = 0; i < 8; i++) sall += red[i];

    const float inv = 1.0f / sall;
    float4 w;
    w.x = e.x * inv; w.y = e.y * inv; w.z = e.z * inv; w.w = e.w * inv;
    ((float4*)&g_wx[ro * TT])[tid] = w;
}

// ---------------------------------------------------------------------------
// Kernel 3: out[b][o][t] = sum_i logits[b,t,i] * g_wx[b][o][i]
// Same no-smem shape; wx[b] (40 KB/batch) is L1-cached, logits L2-resident.
// ---------------------------------------------------------------------------
__global__ __launch_bounds__(CTA, 6) void k_out(const float* __restrict__ logits,
                                                float* __restrict__ out) {
    const int warp = threadIdx.x >> 5;
    const int lane = threadIdx.x & 31;
    const int row0 = blockIdx.x * RPC + warp * RPW;
    const int b = row0 / TT;                  // 16 rows never cross a batch

    float acc[RPW][OO];
    gemv_rows(logits + (size_t)row0 * DD + lane * 4,
              g_wx + (size_t)b * W_FLOATS + lane * 4, acc);

    reduce_store(acc, lane, out + b * OO * TT, row0 % TT, 1.0f, nullptr);
}

// ---------------------------------------------------------------------------
// Launch: inputs per metadata order: logits, decision(unused), W, b
// ---------------------------------------------------------------------------
extern "C" void kernel_launch(void* const* d_in, const int* in_sizes, int n_in,
                              void* d_out, int out_size) {
    const float* logits = (const float*)d_in[0];
    const float* W = (const float*)d_in[2];
    const float* bias = (const float*)d_in[3];
    float* out = (float*)d_out;

    k_scores<<<(BB * TT) / RPC, CTA>>>(logits, W, bias);
    k_softmax<<<BB * OO, 256>>>();
    k_out<<<(BB * TT) / RPC, CTA>>>(logits, out);
}

// round 13
// speedup vs baseline: 1.3636x; 1.3636x over previous
#include <cuda_runtime.h>

// Problem constants (fixed: B=16, T=1024, D=1024, O=10)
#define BB 16
#define TT 1024
#define DD 1024
#define OO 10

#define W_FLOATS (OO * DD)        // 10240 floats = 40 KB

__device__ float g_scores[BB * OO * TT];   // [b][o][t]
__device__ float g_wx[BB * OO * TT];       // softmaxed, [b][o][i]

// ===========================================================================
// k_scores — R10-proven shape (23.5 us): CTA 256 = 4 rowgroups x 2 d-halves,
// 16 rows/CTA, warp covers 4 rows x 512 d with all 16 LDG.128 up-front.
// ===========================================================================
#define S_CTA 256
#define S_WARPS 8
#define S_RPW 4
#define S_RPC 16
#define S_KT 128
#define S_NCH 4
#define S_HALF 512

__device__ __forceinline__ void gemv_half(const float* __restrict__ rbase,
                                          const float* __restrict__ wbase,
                                          float (&acc)[S_RPW][OO]) {
    float4 v[S_NCH][S_RPW];
    #pragma unroll
    for (int kt = 0; kt < S_NCH; kt++)
        #pragma unroll
        for (int r = 0; r < S_RPW; r++)
            v[kt][r] = *(const float4*)(rbase + r * DD + kt * S_KT);

    #pragma unroll
    for (int r = 0; r < S_RPW; r++)
        #pragma unroll
        for (int o = 0; o < OO; o++) acc[r][o] = 0.0f;

    #pragma unroll
    for (int kt = 0; kt < S_NCH; kt++)
        #pragma unroll
        for (int o = 0; o < OO; o++) {
            const float4 w4 = *(const float4*)(wbase + o * DD + kt * S_KT);
            #pragma unroll
            for (int r = 0; r < S_RPW; r++) {
                acc[r][o] = fmaf(v[kt][r].x, w4.x, acc[r][o]);
                acc[r][o] = fmaf(v[kt][r].y, w4.y, acc[r][o]);
                acc[r][o] = fmaf(v[kt][r].z, w4.z, acc[r][o]);
                acc[r][o] = fmaf(v[kt][r].w, w4.w, acc[r][o]);
            }
        }
}

__device__ __forceinline__ void warp_deposit(float (&acc)[S_RPW][OO], int warp,
                                             int lane, float (*partial)[40]) {
    #pragma unroll
    for (int r = 0; r < S_RPW; r++)
        #pragma unroll
        for (int o = 0; o < OO; o++) {
            float x = acc[r][o];
            #pragma unroll
            for (int s = 16; s > 0; s >>= 1)
                x += __shfl_xor_sync(0xffffffffu, x, s);
            if (lane == 0) partial[warp][r * OO + o] = x;
        }
}

__global__ __launch_bounds__(S_CTA, 2) void k_scores(const float* __restrict__ logits,
                                                     const float* __restrict__ W,
                                                     const float* __restrict__ bias) {
    __shared__ float Wsm[W_FLOATS];            // 40 KB
    __shared__ float partial[S_WARPS][40];
    {
        const float4* Wv = (const float4*)W;
        float4* Ws = (float4*)Wsm;
        #pragma unroll
        for (int t = 0; t < 10; t++)
            Ws[threadIdx.x + t * S_CTA] = Wv[threadIdx.x + t * S_CTA];
    }
    __syncthreads();

    const int warp = threadIdx.x >> 5;
    const int lane = threadIdx.x & 31;
    const int rg = warp >> 1;                  // rowgroup 0..3
    const int h = warp & 1;                    // half 0..1
    const int row0 = blockIdx.x * S_RPC + rg * S_RPW;
    const int doff = h * S_HALF + lane * 4;

    float acc[S_RPW][OO];
    gemv_half(logits + (size_t)row0 * DD + doff, Wsm + doff, acc);
    warp_deposit(acc, warp, lane, partial);
    __syncthreads();

    if (threadIdx.x < 160) {
        const int rg2 = threadIdx.x / 40;
        const int idx = threadIdx.x % 40;
        const int r = idx / OO, o = idx % OO;
        const float v = partial[rg2 * 2][idx] + partial[rg2 * 2 + 1][idx];
        const int row = blockIdx.x * S_RPC + rg2 * S_RPW + r;
        const int b = row / TT, t = row % TT;
        g_scores[(b * OO + o) * TT + t] = (v + __ldg(&bias[o])) * (1.0f / OO);
    }
}

// ===========================================================================
// k_softmax — 160 blocks x 256 threads (proven ~1.5 us)
// ===========================================================================
__global__ __launch_bounds__(256) void k_softmax() {
    const int ro = blockIdx.x;
    const int tid = threadIdx.x;
    const float4 v = ((const float4*)&g_scores[ro * TT])[tid];

    __shared__ float red[8];

    float m = fmaxf(fmaxf(v.x, v.y), fmaxf(v.z, v.w));
    #pragma unroll
    for (int s = 16; s > 0; s >>= 1)
        m = fmaxf(m, __shfl_xor_sync(0xffffffffu, m, s));
    if ((tid & 31) == 0) red[tid >> 5] = m;
    __syncthreads();
    float mall = red[0];
    #pragma unroll
    for (int i = 1; i < 8; i++) mall = fmaxf(mall, red[i]);
    __syncthreads();

    float4 e;
    e.x = __expf(v.x - mall);
    e.y = __expf(v.y - mall);
    e.z = __expf(v.z - mall);
    e.w = __expf(v.w - mall);
    float s4 = e.x + e.y + e.z + e.w;
    #pragma unroll
    for (int s = 16; s > 0; s >>= 1)
        s4 += __shfl_xor_sync(0xffffffffu, s4, s);
    if ((tid & 31) == 0) red[tid >> 5] = s4;
    __syncthreads();
    float sall = 0.0f;
    #pragma unroll
    for (int i = 0; i < 8; i++) sall += red[i];

    const float inv = 1.0f / sall;
    float4 w;
    w.x = e.x * inv; w.y = e.y * inv; w.z = e.z * inv; w.w = e.w * inv;
    ((float4*)&g_wx[ro * TT])[tid] = w;
}

// ===========================================================================
// k_out — R1-proven shape (~11 us L2-fed): CTA 256, 32 rows/CTA, 4 rows/warp,
// plain loop (no explicit prefetch), __launch_bounds__(256), regs ~80.
// ===========================================================================
#define O_CTA 256
#define O_RPW 4
#define O_RPC 32

__global__ __launch_bounds__(O_CTA) void k_out(const float* __restrict__ logits,
                                               float* __restrict__ out) {
    __shared__ float Wsm[OO][DD];

    const int row0blk = blockIdx.x * O_RPC;    // 32 rows, batch-aligned
    const int b = row0blk / TT;

    {
        const float4* Wv = (const float4*)(g_wx + (size_t)b * W_FLOATS);
        float4* Ws = (float4*)&Wsm[0][0];
        #pragma unroll
        for (int i = threadIdx.x; i < W_FLOATS / 4; i += O_CTA)
            Ws[i] = Wv[i];
    }
    __syncthreads();

    const int warp = threadIdx.x >> 5;
    const int lane = threadIdx.x & 31;
    const int row0 = row0blk + warp * O_RPW;

    float acc[O_RPW][OO];
    #pragma unroll
    for (int r = 0; r < O_RPW; r++)
        #pragma unroll
        for (int o = 0; o < OO; o++) acc[r][o] = 0.0f;

    for (int k = 0; k < DD / 128; k++) {
        const int d0 = k * 128 + lane * 4;
        float4 lg[O_RPW];
        #pragma unroll
        for (int r = 0; r < O_RPW; r++)
            lg[r] = *(const float4*)&logits[(size_t)(row0 + r) * DD + d0];
        #pragma unroll
        for (int o = 0; o < OO; o++) {
            const float4 w4 = *(const float4*)&Wsm[o][d0];
            #pragma unroll
            for (int r = 0; r < O_RPW; r++) {
                acc[r][o] = fmaf(lg[r].x, w4.x, acc[r][o]);
                acc[r][o] = fmaf(lg[r].y, w4.y, acc[r][o]);
                acc[r][o] = fmaf(lg[r].z, w4.z, acc[r][o]);
                acc[r][o] = fmaf(lg[r].w, w4.w, acc[r][o]);
            }
        }
    }

    #pragma unroll
    for (int r = 0; r < O_RPW; r++)
        #pragma unroll
        for (int o = 0; o < OO; o++) {
            float v = acc[r][o];
            #pragma unroll
            for (int s = 16; s > 0; s >>= 1)
                v += __shfl_xor_sync(0xffffffffu, v, s);
            acc[r][o] = v;
        }

    if (lane == 0) {
        #pragma unroll
        for (int r = 0; r < O_RPW; r++) {
            const int t = (row0 + r) % TT;
            #pragma unroll
            for (int o = 0; o < OO; o++)
                out[(b * OO + o) * TT + t] = acc[r][o];
        }
    }
}

// ---------------------------------------------------------------------------
// Launch: inputs per metadata order: logits, decision(unused), W, b
// ---------------------------------------------------------------------------
extern "C" void kernel_launch(void* const* d_in, const int* in_sizes, int n_in,
                              void* d_out, int out_size) {
    const float* logits = (const float*)d_in[0];
    const float* W = (const float*)d_in[2];
    const float* bias = (const float*)d_in[3];
    float* out = (float*)d_out;

    k_scores<<<(BB * TT) / S_RPC, S_CTA>>>(logits, W, bias);
    k_softmax<<<BB * OO, 256>>>();
    k_out<<<(BB * TT) / O_RPC, O_CTA>>>(logits, out);
}